// round 1
// baseline (speedup 1.0000x reference)
#include <cuda_runtime.h>
#include <math.h>

// Problem constants
#define NN 16384
#define NE 32
#define NH 256
#define NA 64
#define OUTD 5

// ---------------- scratch (device globals; no allocation allowed) ----------------
__device__ float g_TE[NN * NA];        // te = TH @ Wt^T + bt            [N,64]
__device__ float g_V[NN * NH];         // v  = te @ Ws                   [N,256]
__device__ float g_Hagg[NN * NH];      // attention-aggregated hidden    [N,256]
__device__ float g_cat[NN * 2 * NH];   // [x_e || H_e]                   [N,512]
__device__ float g_gates[NN * 3 * NH]; // cat @ Wih^T                    [N,768]
__device__ float g_zrhh[NN * 2 * NH];  // prev @ Whh[0,1]^T              [N,512]
__device__ float g_z[NN * NH];         // sigmoid z gate                 [N,256]
__device__ float g_rh[NN * NH];        // r * prev                       [N,256]
__device__ float g_nh[NN * NH];        // (r*prev) @ Whh[2]^T            [N,256]

// ---------------- generic tiled SGEMM ----------------
// C[m, coff + j] (ldc) = act( sum_k A(m,k) * W[j*wj + k*wk] + bias[j] )
// A is split: k < splitK reads A1 (lda1), else A2 (lda2, k-splitK).
// BM=128, BN=64, BK=16, 256 threads, 8x4 per-thread micro tile.
// Requires: M % 128 == 0, Ncol % 64 == 0, K % 16 == 0, splitK % 16 == 0.
template <int ACT>
__global__ void __launch_bounds__(256) sgemm_k(
    const float* __restrict__ A1, const float* __restrict__ A2, int splitK,
    int lda1, int lda2,
    const float* __restrict__ W, int wj, int wk,
    const float* __restrict__ bias,
    float* __restrict__ C, int ldc, int coff,
    int K)
{
    const int BM = 128, BN = 64, BK = 16;
    __shared__ float As[BK][BM];
    __shared__ float Bs[BK][BN];

    int t = threadIdx.x;
    int tx = t & 15;        // 16 col groups
    int ty = t >> 4;        // 16 row groups
    int row0 = blockIdx.y * BM;
    int col0 = blockIdx.x * BN;

    float acc[8][4];
#pragma unroll
    for (int i = 0; i < 8; i++)
#pragma unroll
        for (int j = 0; j < 4; j++) acc[i][j] = 0.0f;

    for (int k0 = 0; k0 < K; k0 += BK) {
        const float* Asrc;
        int klocal, ldx;
        if (k0 < splitK) { Asrc = A1; klocal = k0; ldx = lda1; }
        else             { Asrc = A2; klocal = k0 - splitK; ldx = lda2; }

        // Load A tile (128x16) as float4 along k, transpose into As[k][m]
#pragma unroll
        for (int i = 0; i < 2; i++) {
            int v = t + i * 256;          // [0,512)
            int r = v >> 2;               // [0,128)
            int kq = (v & 3) * 4;         // {0,4,8,12}
            float4 av = *(const float4*)&Asrc[(size_t)(row0 + r) * ldx + klocal + kq];
            As[kq + 0][r] = av.x;
            As[kq + 1][r] = av.y;
            As[kq + 2][r] = av.z;
            As[kq + 3][r] = av.w;
        }
        // Load B tile (64 j x 16 k) into Bs[k][j]
        {
            int j = t >> 2;               // [0,64)
            int kq = (t & 3) * 4;         // {0,4,8,12}
            const float* wp = &W[(size_t)(col0 + j) * wj + (size_t)(k0 + kq) * wk];
            float4 bv;
            if (wk == 1) {
                bv = *(const float4*)wp;
            } else {
                bv.x = wp[0]; bv.y = wp[wk]; bv.z = wp[2 * wk]; bv.w = wp[3 * wk];
            }
            Bs[kq + 0][j] = bv.x;
            Bs[kq + 1][j] = bv.y;
            Bs[kq + 2][j] = bv.z;
            Bs[kq + 3][j] = bv.w;
        }
        __syncthreads();

#pragma unroll
        for (int kk = 0; kk < BK; kk++) {
            float a[8], b[4];
            *(float4*)&a[0] = *(const float4*)&As[kk][ty * 8];
            *(float4*)&a[4] = *(const float4*)&As[kk][ty * 8 + 4];
            *(float4*)&b[0] = *(const float4*)&Bs[kk][tx * 4];
#pragma unroll
            for (int i = 0; i < 8; i++)
#pragma unroll
                for (int j = 0; j < 4; j++) acc[i][j] = fmaf(a[i], b[j], acc[i][j]);
        }
        __syncthreads();
    }

    float bj[4] = {0.f, 0.f, 0.f, 0.f};
    if (bias) {
#pragma unroll
        for (int j = 0; j < 4; j++) bj[j] = bias[col0 + tx * 4 + j];
    }
#pragma unroll
    for (int i = 0; i < 8; i++) {
        float4 o;
        float v0 = acc[i][0] + bj[0];
        float v1 = acc[i][1] + bj[1];
        float v2 = acc[i][2] + bj[2];
        float v3 = acc[i][3] + bj[3];
        if (ACT == 1) {
            v0 = fmaxf(v0, 0.f); v1 = fmaxf(v1, 0.f);
            v2 = fmaxf(v2, 0.f); v3 = fmaxf(v3, 0.f);
        }
        o.x = v0; o.y = v1; o.z = v2; o.w = v3;
        *(float4*)&C[(size_t)(row0 + ty * 8 + i) * ldc + coff + col0 + tx * 4] = o;
    }
}

// ---------------- attention (one CTA per node) ----------------
// attn[e] = T * dot(spat[n,e,:], v[n,:]);  w = softmax(attn);  Hagg = sum_e w[e]*spat[n,e,:]
// (bs term is softmax-invariant and dropped.)
__global__ void __launch_bounds__(256) attn_kernel(
    const float* __restrict__ spat, const float* __restrict__ V,
    float* __restrict__ Hagg)
{
    __shared__ float sp[NE * NH];   // 32 KB
    __shared__ float vs[NH];
    __shared__ float attn_s[NE];
    __shared__ float ws[NE];

    int n = blockIdx.x;
    int t = threadIdx.x;

    vs[t] = V[(size_t)n * NH + t];
    const float4* g = (const float4*)(spat + (size_t)n * NE * NH);
    float4* s4 = (float4*)sp;
#pragma unroll
    for (int i = 0; i < 8; i++) s4[t + i * 256] = g[t + i * 256];
    __syncthreads();

    int warp = t >> 5, lane = t & 31;
#pragma unroll
    for (int ei = 0; ei < 4; ei++) {
        int e = warp * 4 + ei;
        float s = 0.f;
#pragma unroll
        for (int i = 0; i < 8; i++)
            s = fmaf(sp[e * NH + lane + i * 32], vs[lane + i * 32], s);
#pragma unroll
        for (int o = 16; o; o >>= 1) s += __shfl_xor_sync(0xffffffffu, s, o);
        if (lane == 0) attn_s[e] = s * 4.0f;   // temperature = E/sqrt(A) = 32/8
    }
    __syncthreads();

    if (t < 32) {
        float a = attn_s[t];
        float m = a;
#pragma unroll
        for (int o = 16; o; o >>= 1) m = fmaxf(m, __shfl_xor_sync(0xffffffffu, m, o));
        float p = expf(a - m);
        float ssum = p;
#pragma unroll
        for (int o = 16; o; o >>= 1) ssum += __shfl_xor_sync(0xffffffffu, ssum, o);
        ws[t] = p / ssum;
    }
    __syncthreads();

    float acc = 0.f;
#pragma unroll
    for (int e = 0; e < NE; e++) acc = fmaf(ws[e], sp[e * NH + t], acc);
    Hagg[(size_t)n * NH + t] = acc;
}

// ---------------- x_e = relu(xy @ W_xy^T) into g_cat[:, 0:256] ----------------
__global__ void __launch_bounds__(256) xe_kernel(
    const float* __restrict__ xy, const float* __restrict__ Wxy,
    float* __restrict__ cat)
{
    int n = blockIdx.x;
    int j = threadIdx.x;
    float x0 = xy[n * 2 + 0], x1 = xy[n * 2 + 1];
    float2 w = *(const float2*)&Wxy[j * 2];
    float v = fmaf(x0, w.x, x1 * w.y);
    cat[(size_t)n * 512 + j] = fmaxf(v, 0.f);
}

// ---------------- gate1: z, r*prev ----------------
__global__ void __launch_bounds__(256) gate1_kernel(
    const float* __restrict__ prev, const float* __restrict__ bg,
    float* __restrict__ zout, float* __restrict__ rhout)
{
    int n = blockIdx.x;
    int j = threadIdx.x;
    float ihz = g_gates[(size_t)n * 768 + j];
    float ihr = g_gates[(size_t)n * 768 + 256 + j];
    float hhz = g_zrhh[(size_t)n * 512 + j];
    float hhr = g_zrhh[(size_t)n * 512 + 256 + j];
    float zi = ihz + hhz + bg[j];
    float ri = ihr + hhr + bg[256 + j];
    float z = 1.f / (1.f + expf(-zi));
    float r = 1.f / (1.f + expf(-ri));
    zout[(size_t)n * NH + j] = z;
    rhout[(size_t)n * NH + j] = r * prev[(size_t)n * NH + j];
}

// ---------------- final: n-gate, hidden, predict ----------------
__global__ void __launch_bounds__(256) final_kernel(
    const float* __restrict__ prev, const float* __restrict__ bg,
    const float* __restrict__ Wp, const float* __restrict__ bp,
    float* __restrict__ out_pred, float* __restrict__ out_hidden)
{
    __shared__ float hs[NH];
    int n = blockIdx.x;
    int j = threadIdx.x;
    float nv = g_gates[(size_t)n * 768 + 512 + j] + g_nh[(size_t)n * NH + j] + bg[512 + j];
    nv = fmaxf(nv, 0.f);
    float z = g_z[(size_t)n * NH + j];
    float pv = prev[(size_t)n * NH + j];
    float h = (1.f - z) * nv + z * pv;
    out_hidden[(size_t)n * NH + j] = h;
    hs[j] = h;
    __syncthreads();

    int warp = j >> 5, lane = j & 31;
    if (warp < OUTD) {
        float s = 0.f;
#pragma unroll
        for (int i = 0; i < 8; i++)
            s = fmaf(hs[lane + i * 32], Wp[warp * NH + lane + i * 32], s);
#pragma unroll
        for (int o = 16; o; o >>= 1) s += __shfl_xor_sync(0xffffffffu, s, o);
        if (lane == 0) out_pred[(size_t)n * OUTD + warp] = s + bp[warp];
    }
}

// ---------------- host launcher ----------------
extern "C" void kernel_launch(void* const* d_in, const int* in_sizes, int n_in,
                              void* d_out, int out_size)
{
    const float* xy   = (const float*)d_in[0];
    const float* th   = (const float*)d_in[1];
    const float* spat = (const float*)d_in[2];
    const float* prev = (const float*)d_in[3];
    const float* Wt   = (const float*)d_in[4];
    const float* bt   = (const float*)d_in[5];
    const float* Ws   = (const float*)d_in[6];
    // d_in[7] = bs: softmax-invariant constant shift, unused.
    const float* Wxy  = (const float*)d_in[8];
    const float* Whe  = (const float*)d_in[9];
    const float* Wih  = (const float*)d_in[10];
    const float* Whh  = (const float*)d_in[11];
    const float* bg   = (const float*)d_in[12];
    const float* Wp   = (const float*)d_in[13];
    const float* bp   = (const float*)d_in[14];

    float* out_pred   = (float*)d_out;              // [N, 5]
    float* out_hidden = (float*)d_out + NN * OUTD;  // [N, 256]

    float *pTE, *pV, *pHagg, *pCat, *pGates, *pZrhh, *pZ, *pRh, *pNh;
    cudaGetSymbolAddress((void**)&pTE, g_TE);
    cudaGetSymbolAddress((void**)&pV, g_V);
    cudaGetSymbolAddress((void**)&pHagg, g_Hagg);
    cudaGetSymbolAddress((void**)&pCat, g_cat);
    cudaGetSymbolAddress((void**)&pGates, g_gates);
    cudaGetSymbolAddress((void**)&pZrhh, g_zrhh);
    cudaGetSymbolAddress((void**)&pZ, g_z);
    cudaGetSymbolAddress((void**)&pRh, g_rh);
    cudaGetSymbolAddress((void**)&pNh, g_nh);

    dim3 blk(256);
    const int MB = NN / 128;  // 128 row blocks

    // 1) TE = TH @ Wt^T + bt           [N,64], K=256
    sgemm_k<0><<<dim3(64 / 64, MB), blk>>>(th, th, 256, 256, 256,
                                           Wt, 256, 1, bt, pTE, 64, 0, 256);
    // 2) V = TE @ Ws                   [N,256], K=64  (W[j=h,k=a] = Ws[a*256+h])
    sgemm_k<0><<<dim3(256 / 64, MB), blk>>>(pTE, pTE, 64, 64, 64,
                                            Ws, 1, 256, nullptr, pV, 256, 0, 64);
    // 3) attention -> Hagg
    attn_kernel<<<NN, blk>>>(spat, pV, pHagg);
    // 4) x_e -> g_cat[:, 0:256]
    xe_kernel<<<NN, blk>>>(xy, Wxy, pCat);
    // 5) H_e = relu([TH || Hagg] @ Whe^T) -> g_cat[:, 256:512], K=512 split at 256
    sgemm_k<1><<<dim3(256 / 64, MB), blk>>>(th, pHagg, 256, 256, 256,
                                            Whe, 512, 1, nullptr, pCat, 512, 256, 512);
    // 6) gates_ih = cat @ Wih^T        [N,768], K=512
    sgemm_k<0><<<dim3(768 / 64, MB), blk>>>(pCat, pCat, 512, 512, 512,
                                            Wih, 512, 1, nullptr, pGates, 768, 0, 512);
    // 7) zr_hh = prev @ Whh[0:2]^T     [N,512], K=256
    sgemm_k<0><<<dim3(512 / 64, MB), blk>>>(prev, prev, 256, 256, 256,
                                            Whh, 256, 1, nullptr, pZrhh, 512, 0, 256);
    // 8) z, r*prev
    gate1_kernel<<<NN, blk>>>(prev, bg, pZ, pRh);
    // 9) nh = (r*prev) @ Whh[2]^T      [N,256], K=256
    sgemm_k<0><<<dim3(256 / 64, MB), blk>>>(pRh, pRh, 256, 256, 256,
                                            Whh + 2 * 256 * 256, 256, 1, nullptr,
                                            pNh, 256, 0, 256);
    // 10) hidden + predict
    final_kernel<<<NN, blk>>>(prev, bg, Wp, bp, out_pred, out_hidden);
}

// round 3
// speedup vs baseline: 1.2756x; 1.2756x over previous
#include <cuda_runtime.h>
#include <cuda_bf16.h>
#include <math.h>
#include <stdint.h>

#define NN 16384
#define NE 32
#define NH 256
#define NA 64
#define OUTD 5

// ---------------- scratch (device globals; no allocation allowed) ----------------
__device__ float g_TE[NN * NA];
__device__ float g_V[NN * NH];
__device__ float g_gates[NN * 3 * NH];
__device__ float g_zrhh[NN * 2 * NH];
__device__ float g_z[NN * NH];
__device__ float g_nh[NN * NH];

// bf16 split (hi/lo) buffers
__device__ __nv_bfloat16 g_in1_hi[NN * 512], g_in1_lo[NN * 512];   // [th || Hagg]
__device__ __nv_bfloat16 g_cat_hi[NN * 512], g_cat_lo[NN * 512];   // [x_e || H_e]
__device__ __nv_bfloat16 g_prev_hi[NN * 256], g_prev_lo[NN * 256];
__device__ __nv_bfloat16 g_rh_hi[NN * 256],  g_rh_lo[NN * 256];
__device__ __nv_bfloat16 g_Whe_hi[256 * 512], g_Whe_lo[256 * 512];
__device__ __nv_bfloat16 g_Wih_hi[768 * 512], g_Wih_lo[768 * 512];
__device__ __nv_bfloat16 g_Whh_hi[768 * 256], g_Whh_lo[768 * 256];

// ---------------- PTX helpers (arch-agnostic: ldmatrix/mma.sync/cp.async) ----------------
__device__ __forceinline__ uint32_t smem_u32(const void* p) {
    uint32_t a;
    asm("{ .reg .u64 t; cvta.to.shared.u64 t, %1; cvt.u32.u64 %0, t; }" : "=r"(a) : "l"(p));
    return a;
}
__device__ __forceinline__ void cp_async16(uint32_t s, const void* g) {
    asm volatile("cp.async.cg.shared.global [%0], [%1], 16;" :: "r"(s), "l"(g) : "memory");
}
__device__ __forceinline__ void cp_commit() {
    asm volatile("cp.async.commit_group;" ::: "memory");
}
__device__ __forceinline__ void ldmx4(uint32_t* r, uint32_t addr) {
    asm volatile("ldmatrix.sync.aligned.m8n8.x4.shared.b16 {%0,%1,%2,%3}, [%4];"
                 : "=r"(r[0]), "=r"(r[1]), "=r"(r[2]), "=r"(r[3]) : "r"(addr));
}
__device__ __forceinline__ void mma16816(float* c, const uint32_t* a, uint32_t b0, uint32_t b1) {
    asm volatile(
        "mma.sync.aligned.m16n8k16.row.col.f32.bf16.bf16.f32 "
        "{%0,%1,%2,%3}, {%4,%5,%6,%7}, {%8,%9}, {%0,%1,%2,%3};"
        : "+f"(c[0]), "+f"(c[1]), "+f"(c[2]), "+f"(c[3])
        : "r"(a[0]), "r"(a[1]), "r"(a[2]), "r"(a[3]), "r"(b0), "r"(b1));
}

// ---------------- bf16 double-split GEMM via mma.sync ----------------
// C[row, coff+col] = act( sum_k A[row,k]*W[col,k] ) with A,W = (hi + lo) bf16 split.
// Virtual K' = 3K: term0 = Ahi*Whi, term1 = Ahi*Wlo, term2 = Alo*Whi (fp32 accum).
// BM=BN=128, BK=64. 256 threads, 8 warps (2 M x 4 N), warp tile 64x32.
// OUTMODE: 0 = fp32 store; 2 = relu + bf16 hi/lo split store.
#define MMG_SMEM (2 * 32768)

template <int OUTMODE>
__global__ void __launch_bounds__(256, 2) mma_gemm(
    const __nv_bfloat16* __restrict__ Ah, const __nv_bfloat16* __restrict__ Al, int lda,
    const __nv_bfloat16* __restrict__ Wh, const __nv_bfloat16* __restrict__ Wl, int ldw,
    int K,
    float* __restrict__ Cf,
    __nv_bfloat16* __restrict__ Chi, __nv_bfloat16* __restrict__ Clo,
    int ldc, int coff)
{
    extern __shared__ char smem_raw[];
    const uint32_t base = smem_u32(smem_raw);

    const int t = threadIdx.x, wid = t >> 5, lane = t & 31;
    const int wm = wid & 1, wn = wid >> 1;
    const int row0 = blockIdx.y * 128, col0 = blockIdx.x * 128;

    // tile: 128 rows x 64 bf16 cols, row pitch 128B, 16B-chunk xor swizzle
    auto load_tile = [&](const __nv_bfloat16* src, int ld, int r0, int k0, uint32_t sbase) {
#pragma unroll
        for (int i = 0; i < 4; i++) {
            int idx = t + i * 256;       // 0..1023
            int r = idx >> 3;            // 0..127
            int c = idx & 7;             // 16B chunk
            const char* g = (const char*)(src + (size_t)(r0 + r) * ld + k0 + c * 8);
            uint32_t s = sbase + r * 128 + (((uint32_t)c ^ (r & 7)) * 16);
            cp_async16(s, g);
        }
    };

    const int kper = K >> 6;
    const int iters = 3 * kper;
    auto srcs = [&](int i, const __nv_bfloat16*& As, const __nv_bfloat16*& Ws, int& kk) {
        int term = i / kper;
        kk = (i - term * kper) * 64;
        As = (term < 2) ? Ah : Al;
        Ws = (term == 1) ? Wl : Wh;
    };

    float acc[4][4][4];
#pragma unroll
    for (int a = 0; a < 4; a++)
#pragma unroll
        for (int b = 0; b < 4; b++)
#pragma unroll
            for (int c = 0; c < 4; c++) acc[a][b][c] = 0.f;

    {
        const __nv_bfloat16 *As, *Ws; int kk;
        srcs(0, As, Ws, kk);
        load_tile(As, lda, row0, kk, base);
        load_tile(Ws, ldw, col0, kk, base + 16384);
        cp_commit();
    }

    for (int i = 0; i < iters; i++) {
        int buf = i & 1;
        if (i + 1 < iters) {
            const __nv_bfloat16 *As, *Ws; int kk;
            srcs(i + 1, As, Ws, kk);
            uint32_t nb = base + (uint32_t)(buf ^ 1) * 32768u;
            load_tile(As, lda, row0, kk, nb);
            load_tile(Ws, ldw, col0, kk, nb + 16384);
            cp_commit();
            asm volatile("cp.async.wait_group 1;" ::: "memory");
        } else {
            asm volatile("cp.async.wait_group 0;" ::: "memory");
        }
        __syncthreads();

        uint32_t sA = base + (uint32_t)buf * 32768u;
        uint32_t sB = sA + 16384;
#pragma unroll
        for (int ks = 0; ks < 4; ks++) {
            int kb = ks * 16;
            uint32_t ra[4][4];
#pragma unroll
            for (int im = 0; im < 4; im++) {
                int row = wm * 64 + im * 16 + (lane & 15);
                int kc = (kb >> 3) + (lane >> 4);
                ldmx4(ra[im], sA + row * 128 + (((uint32_t)kc ^ (row & 7)) * 16));
            }
            uint32_t rb[2][4];
#pragma unroll
            for (int ib = 0; ib < 2; ib++) {
                int n = wn * 32 + ib * 16 + ((lane >> 4) ? 8 : 0) + (lane & 7);
                int kc = (kb >> 3) + ((lane >> 3) & 1);
                ldmx4(rb[ib], sB + n * 128 + (((uint32_t)kc ^ (n & 7)) * 16));
            }
#pragma unroll
            for (int im = 0; im < 4; im++)
#pragma unroll
                for (int in = 0; in < 4; in++)
                    mma16816(acc[im][in], ra[im], rb[in >> 1][(in & 1) * 2], rb[in >> 1][(in & 1) * 2 + 1]);
        }
        __syncthreads();
    }

    // epilogue
#pragma unroll
    for (int im = 0; im < 4; im++) {
#pragma unroll
        for (int in = 0; in < 4; in++) {
            int m = row0 + wm * 64 + im * 16 + (lane >> 2);
            int c = coff + col0 + wn * 32 + in * 8 + (lane & 3) * 2;
            float v0 = acc[im][in][0], v1 = acc[im][in][1];
            float v2 = acc[im][in][2], v3 = acc[im][in][3];
            if (OUTMODE == 0) {
                *(float2*)&Cf[(size_t)m * ldc + c] = make_float2(v0, v1);
                *(float2*)&Cf[(size_t)(m + 8) * ldc + c] = make_float2(v2, v3);
            } else {
                v0 = fmaxf(v0, 0.f); v1 = fmaxf(v1, 0.f);
                v2 = fmaxf(v2, 0.f); v3 = fmaxf(v3, 0.f);
                __nv_bfloat162 h0, h1, l0, l1;
                h0.x = __float2bfloat16_rn(v0); h0.y = __float2bfloat16_rn(v1);
                h1.x = __float2bfloat16_rn(v2); h1.y = __float2bfloat16_rn(v3);
                l0.x = __float2bfloat16_rn(v0 - __bfloat162float(h0.x));
                l0.y = __float2bfloat16_rn(v1 - __bfloat162float(h0.y));
                l1.x = __float2bfloat16_rn(v2 - __bfloat162float(h1.x));
                l1.y = __float2bfloat16_rn(v3 - __bfloat162float(h1.y));
                *(__nv_bfloat162*)&Chi[(size_t)m * ldc + c] = h0;
                *(__nv_bfloat162*)&Chi[(size_t)(m + 8) * ldc + c] = h1;
                *(__nv_bfloat162*)&Clo[(size_t)m * ldc + c] = l0;
                *(__nv_bfloat162*)&Clo[(size_t)(m + 8) * ldc + c] = l1;
            }
        }
    }
}

// ---------------- fp32 tiled SGEMM (attention front-end) ----------------
template <int ACT>
__global__ void __launch_bounds__(256) sgemm_k(
    const float* __restrict__ A1, const float* __restrict__ A2, int splitK,
    int lda1, int lda2,
    const float* __restrict__ W, int wj, int wk,
    const float* __restrict__ bias,
    float* __restrict__ C, int ldc, int coff,
    int K)
{
    const int BM = 128, BN = 64, BK = 16;
    __shared__ float As[BK][BM];
    __shared__ float Bs[BK][BN];
    int t = threadIdx.x;
    int tx = t & 15, ty = t >> 4;
    int row0 = blockIdx.y * BM, col0 = blockIdx.x * BN;
    float acc[8][4];
#pragma unroll
    for (int i = 0; i < 8; i++)
#pragma unroll
        for (int j = 0; j < 4; j++) acc[i][j] = 0.0f;

    for (int k0 = 0; k0 < K; k0 += BK) {
        const float* Asrc; int klocal, ldx;
        if (k0 < splitK) { Asrc = A1; klocal = k0; ldx = lda1; }
        else             { Asrc = A2; klocal = k0 - splitK; ldx = lda2; }
#pragma unroll
        for (int i = 0; i < 2; i++) {
            int v = t + i * 256;
            int r = v >> 2;
            int kq = (v & 3) * 4;
            float4 av = *(const float4*)&Asrc[(size_t)(row0 + r) * ldx + klocal + kq];
            As[kq + 0][r] = av.x; As[kq + 1][r] = av.y;
            As[kq + 2][r] = av.z; As[kq + 3][r] = av.w;
        }
        {
            int j = t >> 2;
            int kq = (t & 3) * 4;
            const float* wp = &W[(size_t)(col0 + j) * wj + (size_t)(k0 + kq) * wk];
            float4 bv;
            if (wk == 1) bv = *(const float4*)wp;
            else { bv.x = wp[0]; bv.y = wp[wk]; bv.z = wp[2 * wk]; bv.w = wp[3 * wk]; }
            Bs[kq + 0][j] = bv.x; Bs[kq + 1][j] = bv.y;
            Bs[kq + 2][j] = bv.z; Bs[kq + 3][j] = bv.w;
        }
        __syncthreads();
#pragma unroll
        for (int kk = 0; kk < BK; kk++) {
            float a[8], b[4];
            *(float4*)&a[0] = *(const float4*)&As[kk][ty * 8];
            *(float4*)&a[4] = *(const float4*)&As[kk][ty * 8 + 4];
            *(float4*)&b[0] = *(const float4*)&Bs[kk][tx * 4];
#pragma unroll
            for (int i = 0; i < 8; i++)
#pragma unroll
                for (int j = 0; j < 4; j++) acc[i][j] = fmaf(a[i], b[j], acc[i][j]);
        }
        __syncthreads();
    }
    float bj[4] = {0.f, 0.f, 0.f, 0.f};
    if (bias) {
#pragma unroll
        for (int j = 0; j < 4; j++) bj[j] = bias[col0 + tx * 4 + j];
    }
#pragma unroll
    for (int i = 0; i < 8; i++) {
        float4 o;
        float v0 = acc[i][0] + bj[0], v1 = acc[i][1] + bj[1];
        float v2 = acc[i][2] + bj[2], v3 = acc[i][3] + bj[3];
        if (ACT == 1) {
            v0 = fmaxf(v0, 0.f); v1 = fmaxf(v1, 0.f);
            v2 = fmaxf(v2, 0.f); v3 = fmaxf(v3, 0.f);
        }
        o.x = v0; o.y = v1; o.z = v2; o.w = v3;
        *(float4*)&C[(size_t)(row0 + ty * 8 + i) * ldc + coff + col0 + tx * 4] = o;
    }
}

// ---------------- attention: one CTA per node, writes Hagg as bf16 split ----------------
__global__ void __launch_bounds__(256) attn_kernel(
    const float* __restrict__ spat, const float* __restrict__ V,
    __nv_bfloat16* __restrict__ hi, __nv_bfloat16* __restrict__ lo)
{
    __shared__ float sp[NE * NH];
    __shared__ float vs[NH];
    __shared__ float attn_s[NE];
    __shared__ float ws[NE];

    int n = blockIdx.x;
    int t = threadIdx.x;

    vs[t] = V[(size_t)n * NH + t];
    const float4* g = (const float4*)(spat + (size_t)n * NE * NH);
    float4* s4 = (float4*)sp;
#pragma unroll
    for (int i = 0; i < 8; i++) s4[t + i * 256] = g[t + i * 256];
    __syncthreads();

    int warp = t >> 5, lane = t & 31;
#pragma unroll
    for (int ei = 0; ei < 4; ei++) {
        int e = warp * 4 + ei;
        float s = 0.f;
#pragma unroll
        for (int i = 0; i < 8; i++)
            s = fmaf(sp[e * NH + lane + i * 32], vs[lane + i * 32], s);
#pragma unroll
        for (int o = 16; o; o >>= 1) s += __shfl_xor_sync(0xffffffffu, s, o);
        if (lane == 0) attn_s[e] = s * 4.0f;  // temperature = E/sqrt(A)
    }
    __syncthreads();

    if (t < 32) {
        float a = attn_s[t];
        float m = a;
#pragma unroll
        for (int o = 16; o; o >>= 1) m = fmaxf(m, __shfl_xor_sync(0xffffffffu, m, o));
        float p = expf(a - m);
        float ssum = p;
#pragma unroll
        for (int o = 16; o; o >>= 1) ssum += __shfl_xor_sync(0xffffffffu, ssum, o);
        ws[t] = p / ssum;
    }
    __syncthreads();

    float acc = 0.f;
#pragma unroll
    for (int e = 0; e < NE; e++) acc = fmaf(ws[e], sp[e * NH + t], acc);
    __nv_bfloat16 h = __float2bfloat16_rn(acc);
    size_t off = (size_t)n * 512 + 256 + t;
    hi[off] = h;
    lo[off] = __float2bfloat16_rn(acc - __bfloat162float(h));
}

// ---------------- x_e = relu(xy @ Wxy^T) -> cat[:,0:256] bf16 split ----------------
__global__ void __launch_bounds__(256) xe_kernel(
    const float* __restrict__ xy, const float* __restrict__ Wxy,
    __nv_bfloat16* __restrict__ hi, __nv_bfloat16* __restrict__ lo)
{
    int n = blockIdx.x;
    int j = threadIdx.x;
    float x0 = xy[n * 2 + 0], x1 = xy[n * 2 + 1];
    float2 w = *(const float2*)&Wxy[j * 2];
    float v = fmaxf(fmaf(x0, w.x, x1 * w.y), 0.f);
    __nv_bfloat16 h = __float2bfloat16_rn(v);
    size_t off = (size_t)n * 512 + j;
    hi[off] = h;
    lo[off] = __float2bfloat16_rn(v - __bfloat162float(h));
}

// ---------------- gate1: z, r*prev (bf16 split) ----------------
__global__ void __launch_bounds__(256) gate1_kernel(
    const float* __restrict__ prev, const float* __restrict__ bg,
    float* __restrict__ zout,
    __nv_bfloat16* __restrict__ rhhi, __nv_bfloat16* __restrict__ rhlo)
{
    int n = blockIdx.x;
    int j = threadIdx.x;
    float ihz = g_gates[(size_t)n * 768 + j];
    float ihr = g_gates[(size_t)n * 768 + 256 + j];
    float hhz = g_zrhh[(size_t)n * 512 + j];
    float hhr = g_zrhh[(size_t)n * 512 + 256 + j];
    float z = 1.f / (1.f + expf(-(ihz + hhz + bg[j])));
    float r = 1.f / (1.f + expf(-(ihr + hhr + bg[256 + j])));
    zout[(size_t)n * NH + j] = z;
    float rh = r * prev[(size_t)n * NH + j];
    __nv_bfloat16 h = __float2bfloat16_rn(rh);
    size_t off = (size_t)n * NH + j;
    rhhi[off] = h;
    rhlo[off] = __float2bfloat16_rn(rh - __bfloat162float(h));
}

// ---------------- final: n-gate, hidden, predict ----------------
__global__ void __launch_bounds__(256) final_kernel(
    const float* __restrict__ prev, const float* __restrict__ bg,
    const float* __restrict__ Wp, const float* __restrict__ bp,
    float* __restrict__ out_pred, float* __restrict__ out_hidden)
{
    __shared__ float hs[NH];
    int n = blockIdx.x;
    int j = threadIdx.x;
    float nv = g_gates[(size_t)n * 768 + 512 + j] + g_nh[(size_t)n * NH + j] + bg[512 + j];
    nv = fmaxf(nv, 0.f);
    float z = g_z[(size_t)n * NH + j];
    float pv = prev[(size_t)n * NH + j];
    float h = (1.f - z) * nv + z * pv;
    out_hidden[(size_t)n * NH + j] = h;
    hs[j] = h;
    __syncthreads();

    int warp = j >> 5, lane = j & 31;
    if (warp < OUTD) {
        float s = 0.f;
#pragma unroll
        for (int i = 0; i < 8; i++)
            s = fmaf(hs[lane + i * 32], Wp[warp * NH + lane + i * 32], s);
#pragma unroll
        for (int o = 16; o; o >>= 1) s += __shfl_xor_sync(0xffffffffu, s, o);
        if (lane == 0) out_pred[(size_t)n * OUTD + warp] = s + bp[warp];
    }
}

// ---------------- fp32 -> bf16 (hi, lo) split ----------------
__global__ void split1d(const float* __restrict__ src,
                        __nv_bfloat16* __restrict__ hi, __nv_bfloat16* __restrict__ lo, int n)
{
    int i = blockIdx.x * 256 + threadIdx.x;
    if (i < n) {
        float x = src[i];
        __nv_bfloat16 h = __float2bfloat16_rn(x);
        hi[i] = h;
        lo[i] = __float2bfloat16_rn(x - __bfloat162float(h));
    }
}
// th[N,256] -> in1[:, 0:256] with row stride 512
__global__ void split_th(const float* __restrict__ src,
                         __nv_bfloat16* __restrict__ hi, __nv_bfloat16* __restrict__ lo)
{
    int i = blockIdx.x * 256 + threadIdx.x;
    int n = i >> 8, c = i & 255;
    float x = src[i];
    __nv_bfloat16 h = __float2bfloat16_rn(x);
    size_t off = (size_t)n * 512 + c;
    hi[off] = h;
    lo[off] = __float2bfloat16_rn(x - __bfloat162float(h));
}

// ---------------- host launcher ----------------
extern "C" void kernel_launch(void* const* d_in, const int* in_sizes, int n_in,
                              void* d_out, int out_size)
{
    const float* xy   = (const float*)d_in[0];
    const float* th   = (const float*)d_in[1];
    const float* spat = (const float*)d_in[2];
    const float* prev = (const float*)d_in[3];
    const float* Wt   = (const float*)d_in[4];
    const float* bt   = (const float*)d_in[5];
    const float* Ws   = (const float*)d_in[6];
    // d_in[7] = bs: softmax-invariant, dropped.
    const float* Wxy  = (const float*)d_in[8];
    const float* Whe  = (const float*)d_in[9];
    const float* Wih  = (const float*)d_in[10];
    const float* Whh  = (const float*)d_in[11];
    const float* bg   = (const float*)d_in[12];
    const float* Wp   = (const float*)d_in[13];
    const float* bp   = (const float*)d_in[14];

    float* out_pred   = (float*)d_out;
    float* out_hidden = (float*)d_out + NN * OUTD;

    float *pTE, *pV, *pGates, *pZrhh, *pZ, *pNh;
    __nv_bfloat16 *pIn1h, *pIn1l, *pCath, *pCatl, *pPrevh, *pPrevl, *pRhh, *pRhl;
    __nv_bfloat16 *pWheh, *pWhel, *pWihh, *pWihl, *pWhhh, *pWhhl;
    cudaGetSymbolAddress((void**)&pTE, g_TE);
    cudaGetSymbolAddress((void**)&pV, g_V);
    cudaGetSymbolAddress((void**)&pGates, g_gates);
    cudaGetSymbolAddress((void**)&pZrhh, g_zrhh);
    cudaGetSymbolAddress((void**)&pZ, g_z);
    cudaGetSymbolAddress((void**)&pNh, g_nh);
    cudaGetSymbolAddress((void**)&pIn1h, g_in1_hi);
    cudaGetSymbolAddress((void**)&pIn1l, g_in1_lo);
    cudaGetSymbolAddress((void**)&pCath, g_cat_hi);
    cudaGetSymbolAddress((void**)&pCatl, g_cat_lo);
    cudaGetSymbolAddress((void**)&pPrevh, g_prev_hi);
    cudaGetSymbolAddress((void**)&pPrevl, g_prev_lo);
    cudaGetSymbolAddress((void**)&pRhh, g_rh_hi);
    cudaGetSymbolAddress((void**)&pRhl, g_rh_lo);
    cudaGetSymbolAddress((void**)&pWheh, g_Whe_hi);
    cudaGetSymbolAddress((void**)&pWhel, g_Whe_lo);
    cudaGetSymbolAddress((void**)&pWihh, g_Wih_hi);
    cudaGetSymbolAddress((void**)&pWihl, g_Wih_lo);
    cudaGetSymbolAddress((void**)&pWhhh, g_Whh_hi);
    cudaGetSymbolAddress((void**)&pWhhl, g_Whh_lo);

    cudaFuncSetAttribute(mma_gemm<0>, cudaFuncAttributeMaxDynamicSharedMemorySize, MMG_SMEM);
    cudaFuncSetAttribute(mma_gemm<2>, cudaFuncAttributeMaxDynamicSharedMemorySize, MMG_SMEM);

    dim3 blk(256);
    const int MB = NN / 128;

    // conversions
    split1d<<<(256 * 512 + 255) / 256, blk>>>(Whe, pWheh, pWhel, 256 * 512);
    split1d<<<(768 * 512 + 255) / 256, blk>>>(Wih, pWihh, pWihl, 768 * 512);
    split1d<<<(768 * 256 + 255) / 256, blk>>>(Whh, pWhhh, pWhhl, 768 * 256);
    split1d<<<(NN * 256 + 255) / 256, blk>>>(prev, pPrevh, pPrevl, NN * 256);
    split_th<<<NN, blk>>>(th, pIn1h, pIn1l);

    // attention front-end (fp32)
    sgemm_k<0><<<dim3(1, MB), blk>>>(th, th, 256, 256, 256, Wt, 256, 1, bt, pTE, 64, 0, 256);
    sgemm_k<0><<<dim3(4, MB), blk>>>(pTE, pTE, 64, 64, 64, Ws, 1, 256, nullptr, pV, 256, 0, 64);
    attn_kernel<<<NN, blk>>>(spat, pV, pIn1h, pIn1l);
    xe_kernel<<<NN, blk>>>(xy, Wxy, pCath, pCatl);

    // H_e = relu(in1 @ Whe^T)  -> cat[:,256:512] (bf16 split)
    mma_gemm<2><<<dim3(2, MB), blk, MMG_SMEM>>>(
        pIn1h, pIn1l, 512, pWheh, pWhel, 512, 512,
        nullptr, pCath, pCatl, 512, 256);
    // gates_ih = cat @ Wih^T   -> g_gates fp32 [N,768]
    mma_gemm<0><<<dim3(6, MB), blk, MMG_SMEM>>>(
        pCath, pCatl, 512, pWihh, pWihl, 512, 512,
        pGates, nullptr, nullptr, 768, 0);
    // zr_hh = prev @ Whh[0:2]^T -> g_zrhh fp32 [N,512]
    mma_gemm<0><<<dim3(4, MB), blk, MMG_SMEM>>>(
        pPrevh, pPrevl, 256, pWhhh, pWhhl, 256, 256,
        pZrhh, nullptr, nullptr, 512, 0);
    // gates
    gate1_kernel<<<NN, blk>>>(prev, bg, pZ, pRhh, pRhl);
    // nh = (r*prev) @ Whh[2]^T -> g_nh fp32 [N,256]
    mma_gemm<0><<<dim3(2, MB), blk, MMG_SMEM>>>(
        pRhh, pRhl, 256, pWhhh + 512 * 256, pWhhl + 512 * 256, 256, 256,
        pNh, nullptr, nullptr, 256, 0);
    // output
    final_kernel<<<NN, blk>>>(prev, bg, Wp, bp, out_pred, out_hidden);
}

// round 4
// speedup vs baseline: 1.4684x; 1.1512x over previous
#include <cuda_runtime.h>
#include <cuda_bf16.h>
#include <math.h>
#include <stdint.h>

#define NN 16384
#define NE 32
#define NH 256
#define OUTD 5

typedef __nv_bfloat16 bf16;

// ---------------- scratch (device globals) ----------------
__device__ __align__(16) float g_M[256 * 256 + 256];     // fused Wt^T@Ws, then bt@Ws
__device__ __align__(16) float g_V[NN * NH];
__device__ __align__(16) float g_z[NN * NH];

__device__ __align__(16) bf16 g_in1_hi[NN * 512], g_in1_lo[NN * 512];   // [th || Hagg]
__device__ __align__(16) bf16 g_cat_hi[NN * 512], g_cat_lo[NN * 512];   // [x_e || H_e]
__device__ __align__(16) bf16 g_prev_hi[NN * 256], g_prev_lo[NN * 256];
__device__ __align__(16) bf16 g_rh_hi[NN * 256],  g_rh_lo[NN * 256];
__device__ __align__(16) bf16 g_Whe_hi[256 * 512], g_Whe_lo[256 * 512];
__device__ __align__(16) bf16 g_Uzr_hi[512 * 768], g_Uzr_lo[512 * 768]; // [Wih_z|Whh_z ; Wih_r|Whh_r]
__device__ __align__(16) bf16 g_Un_hi[256 * 768],  g_Un_lo[256 * 768];  // [Wih_n|Whh_n]

// ---------------- PTX helpers ----------------
__device__ __forceinline__ uint32_t smem_u32(const void* p) {
    uint32_t a;
    asm("{ .reg .u64 t; cvta.to.shared.u64 t, %1; cvt.u32.u64 %0, t; }" : "=r"(a) : "l"(p));
    return a;
}
__device__ __forceinline__ void cp_async16(uint32_t s, const void* g) {
    asm volatile("cp.async.cg.shared.global [%0], [%1], 16;" :: "r"(s), "l"(g) : "memory");
}
__device__ __forceinline__ void cp_commit() {
    asm volatile("cp.async.commit_group;" ::: "memory");
}
__device__ __forceinline__ void ldmx4(uint32_t* r, uint32_t addr) {
    asm volatile("ldmatrix.sync.aligned.m8n8.x4.shared.b16 {%0,%1,%2,%3}, [%4];"
                 : "=r"(r[0]), "=r"(r[1]), "=r"(r[2]), "=r"(r[3]) : "r"(addr));
}
__device__ __forceinline__ void mma16816(float* c, const uint32_t* a, uint32_t b0, uint32_t b1) {
    asm volatile(
        "mma.sync.aligned.m16n8k16.row.col.f32.bf16.bf16.f32 "
        "{%0,%1,%2,%3}, {%4,%5,%6,%7}, {%8,%9}, {%0,%1,%2,%3};"
        : "+f"(c[0]), "+f"(c[1]), "+f"(c[2]), "+f"(c[3])
        : "r"(a[0]), "r"(a[1]), "r"(a[2]), "r"(a[3]), "r"(b0), "r"(b1));
}
__device__ __forceinline__ void split_write(bf16* hi, bf16* lo, size_t off, float x) {
    bf16 h = __float2bfloat16_rn(x);
    hi[off] = h;
    lo[off] = __float2bfloat16_rn(x - __bfloat162float(h));
}

// ---------------- bf16 double-split GEMM v2 (mma.sync) ----------------
// Per 32-K chunk: 4 tiles (Ahi,Alo,Whi,Wlo) loaded once; 3 MMA terms
// (hi*hi + hi*lo + lo*hi) run from registers. 3-stage cp.async pipeline.
// BM=BN=128, BK=32, 256 threads, 8 warps (2M x 4N), warp tile 64x32.
// Tile pitch 80B (32 bf16 + 16B pad) -> conflict-free ldmatrix.
// OUTMODE: 2 = relu+bf16 split; 3 = zr epilogue; 4 = n/final epilogue.
#define ST 40960
#define MMG_SMEM (3 * ST)

template <int OUTMODE>
__global__ void __launch_bounds__(256) mma3(
    const bf16* __restrict__ A1h, const bf16* __restrict__ A1l, int lda1,
    const bf16* __restrict__ A2h, const bf16* __restrict__ A2l, int lda2, int splitK,
    const bf16* __restrict__ Wh, const bf16* __restrict__ Wl, int ldw, int K,
    bf16* __restrict__ Chi, bf16* __restrict__ Clo, int ldc, int coff,
    const float* __restrict__ bg, const float* __restrict__ prevp,
    float* __restrict__ zbuf,
    bf16* __restrict__ rhhi, bf16* __restrict__ rhlo,
    float* __restrict__ outh)
{
    extern __shared__ char sm[];
    const uint32_t base = smem_u32(sm);
    const int t = threadIdx.x, wid = t >> 5, lane = t & 31;
    const int wm = wid & 1, wn = wid >> 1;
    const int row0 = blockIdx.y * 128, col0 = blockIdx.x * 128;
    const int chunks = K >> 5;

    auto load_stage = [&](int s, int ck) {
        int k0 = ck * 32;
        const bf16 *ah, *al;
        int lda, kk;
        if (k0 < splitK) { ah = A1h; al = A1l; lda = lda1; kk = k0; }
        else             { ah = A2h; al = A2l; lda = lda2; kk = k0 - splitK; }
        uint32_t sb = base + (uint32_t)s * ST;
#pragma unroll
        for (int half = 0; half < 2; half++) {
            int idx = t + half * 256;   // 0..511
            int r = idx >> 2, c = idx & 3;
            uint32_t so = r * 80 + c * 16;
            cp_async16(sb + so,          ah + (size_t)(row0 + r) * lda + kk + c * 8);
            cp_async16(sb + 10240 + so,  al + (size_t)(row0 + r) * lda + kk + c * 8);
            cp_async16(sb + 20480 + so,  Wh + (size_t)(col0 + r) * ldw + k0 + c * 8);
            cp_async16(sb + 30720 + so,  Wl + (size_t)(col0 + r) * ldw + k0 + c * 8);
        }
        cp_commit();
    };

    float acc[4][4][4];
#pragma unroll
    for (int a = 0; a < 4; a++)
#pragma unroll
        for (int b = 0; b < 4; b++)
#pragma unroll
            for (int c = 0; c < 4; c++) acc[a][b][c] = 0.f;

    load_stage(0, 0);
    load_stage(1, 1);

    for (int i = 0; i < chunks; i++) {
        uint32_t sb = base + (uint32_t)(i % 3) * ST;
        if (i + 2 < chunks) load_stage((i + 2) % 3, i + 2);
        if (i + 1 < chunks) asm volatile("cp.async.wait_group 1;" ::: "memory");
        else                asm volatile("cp.async.wait_group 0;" ::: "memory");
        __syncthreads();

#pragma unroll
        for (int ks = 0; ks < 2; ks++) {
            int kb = ks * 16;
            uint32_t ra[4][4], rbh[2][4], rbl[2][4];
            int arow[4], akc;
            akc = (kb >> 3) + (lane >> 4);
#pragma unroll
            for (int im = 0; im < 4; im++) {
                arow[im] = wm * 64 + im * 16 + (lane & 15);
                ldmx4(ra[im], sb + arow[im] * 80 + akc * 16);   // A hi
            }
#pragma unroll
            for (int ib = 0; ib < 2; ib++) {
                int n = wn * 32 + ib * 16 + ((lane & 16) ? 8 : 0) + (lane & 7);
                int kc = (kb >> 3) + ((lane >> 3) & 1);
                ldmx4(rbh[ib], sb + 20480 + n * 80 + kc * 16);  // W hi
                ldmx4(rbl[ib], sb + 30720 + n * 80 + kc * 16);  // W lo
            }
            // term: Ahi * Whi
#pragma unroll
            for (int im = 0; im < 4; im++)
#pragma unroll
                for (int in = 0; in < 4; in++)
                    mma16816(acc[im][in], ra[im], rbh[in >> 1][(in & 1) * 2], rbh[in >> 1][(in & 1) * 2 + 1]);
            // term: Ahi * Wlo
#pragma unroll
            for (int im = 0; im < 4; im++)
#pragma unroll
                for (int in = 0; in < 4; in++)
                    mma16816(acc[im][in], ra[im], rbl[in >> 1][(in & 1) * 2], rbl[in >> 1][(in & 1) * 2 + 1]);
            // reload A lo, term: Alo * Whi
#pragma unroll
            for (int im = 0; im < 4; im++)
                ldmx4(ra[im], sb + 10240 + arow[im] * 80 + akc * 16);
#pragma unroll
            for (int im = 0; im < 4; im++)
#pragma unroll
                for (int in = 0; in < 4; in++)
                    mma16816(acc[im][in], ra[im], rbh[in >> 1][(in & 1) * 2], rbh[in >> 1][(in & 1) * 2 + 1]);
        }
        __syncthreads();
    }

    // ---------------- epilogue ----------------
    auto emit = [&](int mm, int cc, float v) {
        if (OUTMODE == 2) {
            float x = fmaxf(v, 0.f);
            split_write(Chi, Clo, (size_t)mm * ldc + coff + cc, x);
        } else if (OUTMODE == 3) {
            float s = 1.f / (1.f + expf(-(v + bg[cc])));
            if (cc < 256) {
                zbuf[(size_t)mm * 256 + cc] = s;
            } else {
                int j = cc - 256;
                float rh = s * prevp[(size_t)mm * 256 + j];
                split_write(rhhi, rhlo, (size_t)mm * 256 + j, rh);
            }
        } else {  // OUTMODE == 4
            float nv = fmaxf(v + bg[512 + cc], 0.f);
            float z = zbuf[(size_t)mm * 256 + cc];
            float pv = prevp[(size_t)mm * 256 + cc];
            outh[(size_t)mm * 256 + cc] = (1.f - z) * nv + z * pv;
        }
    };
#pragma unroll
    for (int im = 0; im < 4; im++) {
#pragma unroll
        for (int in = 0; in < 4; in++) {
            int m = row0 + wm * 64 + im * 16 + (lane >> 2);
            int c = col0 + wn * 32 + in * 8 + (lane & 3) * 2;
            emit(m, c, acc[im][in][0]);
            emit(m, c + 1, acc[im][in][1]);
            emit(m + 8, c, acc[im][in][2]);
            emit(m + 8, c + 1, acc[im][in][3]);
        }
    }
}

// ---------------- fp32 tiled SGEMM (V = th @ M + c) ----------------
__global__ void __launch_bounds__(256) sgemm_v(
    const float* __restrict__ A, const float* __restrict__ M,
    const float* __restrict__ cvec, float* __restrict__ C)
{
    const int BM = 128, BN = 64, BK = 16;
    __shared__ float As[BK][BM];
    __shared__ float Bs[BK][BN];
    int t = threadIdx.x;
    int tx = t & 15, ty = t >> 4;
    int row0 = blockIdx.y * BM, col0 = blockIdx.x * BN;
    float acc[8][4];
#pragma unroll
    for (int i = 0; i < 8; i++)
#pragma unroll
        for (int j = 0; j < 4; j++) acc[i][j] = 0.0f;

    for (int k0 = 0; k0 < 256; k0 += BK) {
#pragma unroll
        for (int i = 0; i < 2; i++) {
            int v = t + i * 256;
            int r = v >> 2;
            int kq = (v & 3) * 4;
            float4 av = *(const float4*)&A[(size_t)(row0 + r) * 256 + k0 + kq];
            As[kq + 0][r] = av.x; As[kq + 1][r] = av.y;
            As[kq + 2][r] = av.z; As[kq + 3][r] = av.w;
        }
        {
            int j = t >> 2;
            int kq = (t & 3) * 4;
#pragma unroll
            for (int q = 0; q < 4; q++)
                Bs[kq + q][j] = M[(size_t)(k0 + kq + q) * 256 + col0 + j];
        }
        __syncthreads();
#pragma unroll
        for (int kk = 0; kk < BK; kk++) {
            float a[8], b[4];
            *(float4*)&a[0] = *(const float4*)&As[kk][ty * 8];
            *(float4*)&a[4] = *(const float4*)&As[kk][ty * 8 + 4];
            *(float4*)&b[0] = *(const float4*)&Bs[kk][tx * 4];
#pragma unroll
            for (int i = 0; i < 8; i++)
#pragma unroll
                for (int j = 0; j < 4; j++) acc[i][j] = fmaf(a[i], b[j], acc[i][j]);
        }
        __syncthreads();
    }
#pragma unroll
    for (int i = 0; i < 8; i++) {
        float4 o;
        o.x = acc[i][0] + cvec[col0 + tx * 4 + 0];
        o.y = acc[i][1] + cvec[col0 + tx * 4 + 1];
        o.z = acc[i][2] + cvec[col0 + tx * 4 + 2];
        o.w = acc[i][3] + cvec[col0 + tx * 4 + 3];
        *(float4*)&C[(size_t)(row0 + ty * 8 + i) * 256 + col0 + tx * 4] = o;
    }
}

// ---------------- M = Wt^T @ Ws, cvec = bt @ Ws ----------------
__global__ void computeM(const float* __restrict__ Wt, const float* __restrict__ Ws,
                         const float* __restrict__ bt, float* __restrict__ M,
                         float* __restrict__ cvec)
{
    int k = blockIdx.x, j = threadIdx.x;
    float s = 0.f;
#pragma unroll 8
    for (int a = 0; a < 64; a++) s = fmaf(Wt[a * 256 + k], Ws[a * 256 + j], s);
    M[k * 256 + j] = s;
    if (k == 0) {
        float c = 0.f;
#pragma unroll 8
        for (int a = 0; a < 64; a++) c = fmaf(bt[a], Ws[a * 256 + j], c);
        cvec[j] = c;
    }
}

// ---------------- attention (unchanged core; writes in1 cols 256:512) ----------------
__global__ void __launch_bounds__(256) attn_kernel(
    const float* __restrict__ spat, const float* __restrict__ V,
    bf16* __restrict__ hi, bf16* __restrict__ lo)
{
    __shared__ float sp[NE * NH];
    __shared__ float vs[NH];
    __shared__ float attn_s[NE];
    __shared__ float ws[NE];

    int n = blockIdx.x;
    int t = threadIdx.x;

    vs[t] = V[(size_t)n * NH + t];
    const float4* g = (const float4*)(spat + (size_t)n * NE * NH);
    float4* s4 = (float4*)sp;
#pragma unroll
    for (int i = 0; i < 8; i++) s4[t + i * 256] = g[t + i * 256];
    __syncthreads();

    int warp = t >> 5, lane = t & 31;
#pragma unroll
    for (int ei = 0; ei < 4; ei++) {
        int e = warp * 4 + ei;
        float s = 0.f;
#pragma unroll
        for (int i = 0; i < 8; i++)
            s = fmaf(sp[e * NH + lane + i * 32], vs[lane + i * 32], s);
#pragma unroll
        for (int o = 16; o; o >>= 1) s += __shfl_xor_sync(0xffffffffu, s, o);
        if (lane == 0) attn_s[e] = s * 4.0f;  // temperature = E/sqrt(A)
    }
    __syncthreads();

    if (t < 32) {
        float a = attn_s[t];
        float m = a;
#pragma unroll
        for (int o = 16; o; o >>= 1) m = fmaxf(m, __shfl_xor_sync(0xffffffffu, m, o));
        float p = expf(a - m);
        float ssum = p;
#pragma unroll
        for (int o = 16; o; o >>= 1) ssum += __shfl_xor_sync(0xffffffffu, ssum, o);
        ws[t] = p / ssum;
    }
    __syncthreads();

    float acc = 0.f;
#pragma unroll
    for (int e = 0; e < NE; e++) acc = fmaf(ws[e], sp[e * NH + t], acc);
    split_write(hi, lo, (size_t)n * 512 + 256 + t, acc);
}

// ---------------- x_e -> cat[:,0:256] ----------------
__global__ void __launch_bounds__(256) xe_kernel(
    const float* __restrict__ xy, const float* __restrict__ Wxy,
    bf16* __restrict__ hi, bf16* __restrict__ lo)
{
    int n = blockIdx.x;
    int j = threadIdx.x;
    float x0 = xy[n * 2 + 0], x1 = xy[n * 2 + 1];
    float2 w = *(const float2*)&Wxy[j * 2];
    float v = fmaxf(fmaf(x0, w.x, x1 * w.y), 0.f);
    split_write(hi, lo, (size_t)n * 512 + j, v);
}

// ---------------- prev + th splits ----------------
__global__ void __launch_bounds__(256) split_prev_th(
    const float* __restrict__ prev, const float* __restrict__ th,
    bf16* __restrict__ ph, bf16* __restrict__ pl,
    bf16* __restrict__ i1h, bf16* __restrict__ i1l)
{
    int n = blockIdx.x, c = threadIdx.x;
    size_t i = (size_t)n * 256 + c;
    split_write(ph, pl, i, prev[i]);
    split_write(i1h, i1l, (size_t)n * 512 + c, th[i]);
}

// ---------------- weight merge + split ----------------
__global__ void merge_weights(
    const float* __restrict__ Whe, const float* __restrict__ Wih, const float* __restrict__ Whh,
    bf16* __restrict__ WheH, bf16* __restrict__ WheL,
    bf16* __restrict__ UzrH, bf16* __restrict__ UzrL,
    bf16* __restrict__ UnH,  bf16* __restrict__ UnL)
{
    int i = blockIdx.x * 256 + threadIdx.x;
    float x;
    if (i < 131072) {
        x = Whe[i];
        split_write(WheH, WheL, i, x);
    } else if (i < 131072 + 393216) {
        int q = i - 131072;
        int j = q / 768, k = q - j * 768;
        int g = j >> 8, r = j & 255;
        x = (k < 512) ? Wih[g * 131072 + r * 512 + k] : Whh[g * 65536 + r * 256 + (k - 512)];
        split_write(UzrH, UzrL, q, x);
    } else {
        int q = i - 524288;
        int j = q / 768, k = q - j * 768;
        x = (k < 512) ? Wih[262144 + j * 512 + k] : Whh[131072 + j * 256 + (k - 512)];
        split_write(UnH, UnL, q, x);
    }
}

// ---------------- predict head ----------------
__global__ void __launch_bounds__(256) predict_kernel(
    const float* __restrict__ hid, const float* __restrict__ Wp,
    const float* __restrict__ bp, float* __restrict__ out)
{
    __shared__ float hs[NH];
    int n = blockIdx.x, t = threadIdx.x;
    hs[t] = hid[(size_t)n * NH + t];
    __syncthreads();
    int w = t >> 5, lane = t & 31;
    if (w < OUTD) {
        float s = 0.f;
#pragma unroll
        for (int i = 0; i < 8; i++)
            s = fmaf(hs[lane + i * 32], Wp[w * NH + lane + i * 32], s);
#pragma unroll
        for (int o = 16; o; o >>= 1) s += __shfl_xor_sync(0xffffffffu, s, o);
        if (lane == 0) out[(size_t)n * OUTD + w] = s + bp[w];
    }
}

// ---------------- host launcher ----------------
extern "C" void kernel_launch(void* const* d_in, const int* in_sizes, int n_in,
                              void* d_out, int out_size)
{
    const float* xy   = (const float*)d_in[0];
    const float* th   = (const float*)d_in[1];
    const float* spat = (const float*)d_in[2];
    const float* prev = (const float*)d_in[3];
    const float* Wt   = (const float*)d_in[4];
    const float* bt   = (const float*)d_in[5];
    const float* Ws   = (const float*)d_in[6];
    // d_in[7] = bs: softmax-invariant, dropped.
    const float* Wxy  = (const float*)d_in[8];
    const float* Whe  = (const float*)d_in[9];
    const float* Wih  = (const float*)d_in[10];
    const float* Whh  = (const float*)d_in[11];
    const float* bg   = (const float*)d_in[12];
    const float* Wp   = (const float*)d_in[13];
    const float* bp   = (const float*)d_in[14];

    float* out_pred   = (float*)d_out;
    float* out_hidden = (float*)d_out + NN * OUTD;

    float *pM, *pV, *pZ;
    bf16 *pIn1h, *pIn1l, *pCath, *pCatl, *pPrevh, *pPrevl, *pRhh, *pRhl;
    bf16 *pWheh, *pWhel, *pUzrh, *pUzrl, *pUnh, *pUnl;
    cudaGetSymbolAddress((void**)&pM, g_M);
    cudaGetSymbolAddress((void**)&pV, g_V);
    cudaGetSymbolAddress((void**)&pZ, g_z);
    cudaGetSymbolAddress((void**)&pIn1h, g_in1_hi);
    cudaGetSymbolAddress((void**)&pIn1l, g_in1_lo);
    cudaGetSymbolAddress((void**)&pCath, g_cat_hi);
    cudaGetSymbolAddress((void**)&pCatl, g_cat_lo);
    cudaGetSymbolAddress((void**)&pPrevh, g_prev_hi);
    cudaGetSymbolAddress((void**)&pPrevl, g_prev_lo);
    cudaGetSymbolAddress((void**)&pRhh, g_rh_hi);
    cudaGetSymbolAddress((void**)&pRhl, g_rh_lo);
    cudaGetSymbolAddress((void**)&pWheh, g_Whe_hi);
    cudaGetSymbolAddress((void**)&pWhel, g_Whe_lo);
    cudaGetSymbolAddress((void**)&pUzrh, g_Uzr_hi);
    cudaGetSymbolAddress((void**)&pUzrl, g_Uzr_lo);
    cudaGetSymbolAddress((void**)&pUnh, g_Un_hi);
    cudaGetSymbolAddress((void**)&pUnl, g_Un_lo);

    cudaFuncSetAttribute(mma3<2>, cudaFuncAttributeMaxDynamicSharedMemorySize, MMG_SMEM);
    cudaFuncSetAttribute(mma3<3>, cudaFuncAttributeMaxDynamicSharedMemorySize, MMG_SMEM);
    cudaFuncSetAttribute(mma3<4>, cudaFuncAttributeMaxDynamicSharedMemorySize, MMG_SMEM);

    dim3 blk(256);
    const int MB = NN / 128;

    // prep
    merge_weights<<<2816, blk>>>(Whe, Wih, Whh, pWheh, pWhel, pUzrh, pUzrl, pUnh, pUnl);
    computeM<<<256, blk>>>(Wt, Ws, bt, pM, pM + 65536);
    split_prev_th<<<NN, blk>>>(prev, th, pPrevh, pPrevl, pIn1h, pIn1l);

    // attention front-end
    sgemm_v<<<dim3(4, MB), blk>>>(th, pM, pM + 65536, pV);
    attn_kernel<<<NN, blk>>>(spat, pV, pIn1h, pIn1l);
    xe_kernel<<<NN, blk>>>(xy, Wxy, pCath, pCatl);

    // H_e = relu(in1 @ Whe^T) -> cat[:,256:512]
    mma3<2><<<dim3(2, MB), blk, MMG_SMEM>>>(
        pIn1h, pIn1l, 512, pIn1h, pIn1l, 512, 512,
        pWheh, pWhel, 512, 512,
        pCath, pCatl, 512, 256, nullptr, nullptr, nullptr, nullptr, nullptr, nullptr);

    // z,r = sigmoid([cat||prev] @ Uzr^T + bg) ; writes g_z and rh=r*prev (split)
    mma3<3><<<dim3(4, MB), blk, MMG_SMEM>>>(
        pCath, pCatl, 512, pPrevh, pPrevl, 256, 512,
        pUzrh, pUzrl, 768, 768,
        nullptr, nullptr, 0, 0, bg, prev, pZ, pRhh, pRhl, nullptr);

    // n = relu([cat||rh] @ Un^T + bg); hidden = (1-z)n + z*prev -> out_hidden
    mma3<4><<<dim3(2, MB), blk, MMG_SMEM>>>(
        pCath, pCatl, 512, pRhh, pRhl, 256, 512,
        pUnh, pUnl, 768, 768,
        nullptr, nullptr, 0, 0, bg, prev, pZ, nullptr, nullptr, out_hidden);

    // predict head
    predict_kernel<<<NN, blk>>>(out_hidden, Wp, bp, out_pred);
}

// round 5
// speedup vs baseline: 1.8231x; 1.2415x over previous
#include <cuda_runtime.h>
#include <cuda_bf16.h>
#include <math.h>
#include <stdint.h>

#define NN 16384
#define NE 32
#define NH 256
#define OUTD 5

typedef __nv_bfloat16 bf16;

// ---------------- scratch (device globals) ----------------
__device__ __align__(16) float g_cvec[256];
__device__ __align__(16) float g_V[NN * NH];
__device__ __align__(16) float g_z[NN * NH];

__device__ __align__(16) bf16 g_Mt_hi[256 * 256], g_Mt_lo[256 * 256];  // (Wt^T@Ws)^T split
__device__ __align__(16) bf16 g_in1_hi[NN * 512], g_in1_lo[NN * 512];  // [th || Hagg]
__device__ __align__(16) bf16 g_cat_hi[NN * 512], g_cat_lo[NN * 512];  // [x_e || H_e]
__device__ __align__(16) bf16 g_prev_hi[NN * 256], g_prev_lo[NN * 256];
__device__ __align__(16) bf16 g_rh_hi[NN * 256],  g_rh_lo[NN * 256];
__device__ __align__(16) bf16 g_Whe_hi[256 * 512], g_Whe_lo[256 * 512];
__device__ __align__(16) bf16 g_Uzr_hi[512 * 768], g_Uzr_lo[512 * 768];
__device__ __align__(16) bf16 g_Un_hi[256 * 768],  g_Un_lo[256 * 768];

// ---------------- PTX helpers ----------------
__device__ __forceinline__ uint32_t smem_u32(const void* p) {
    uint32_t a;
    asm("{ .reg .u64 t; cvta.to.shared.u64 t, %1; cvt.u32.u64 %0, t; }" : "=r"(a) : "l"(p));
    return a;
}
__device__ __forceinline__ void cp_async16(uint32_t s, const void* g) {
    asm volatile("cp.async.cg.shared.global [%0], [%1], 16;" :: "r"(s), "l"(g) : "memory");
}
__device__ __forceinline__ void cp_commit() {
    asm volatile("cp.async.commit_group;" ::: "memory");
}
__device__ __forceinline__ void ldmx4(uint32_t* r, uint32_t addr) {
    asm volatile("ldmatrix.sync.aligned.m8n8.x4.shared.b16 {%0,%1,%2,%3}, [%4];"
                 : "=r"(r[0]), "=r"(r[1]), "=r"(r[2]), "=r"(r[3]) : "r"(addr));
}
__device__ __forceinline__ void mma16816(float* c, const uint32_t* a, uint32_t b0, uint32_t b1) {
    asm volatile(
        "mma.sync.aligned.m16n8k16.row.col.f32.bf16.bf16.f32 "
        "{%0,%1,%2,%3}, {%4,%5,%6,%7}, {%8,%9}, {%0,%1,%2,%3};"
        : "+f"(c[0]), "+f"(c[1]), "+f"(c[2]), "+f"(c[3])
        : "r"(a[0]), "r"(a[1]), "r"(a[2]), "r"(a[3]), "r"(b0), "r"(b1));
}
__device__ __forceinline__ void split_write(bf16* hi, bf16* lo, size_t off, float x) {
    bf16 h = __float2bfloat16_rn(x);
    hi[off] = h;
    lo[off] = __float2bfloat16_rn(x - __bfloat162float(h));
}

// ---------------- bf16 double-split GEMM (mma.sync), 2-stage, 2 CTAs/SM ----------------
// OUTMODE: 2 = relu+bf16 split; 3 = zr epilogue; 4 = n/final epilogue; 5 = fp32+bias.
#define ST 40960
#define MMG_SMEM (2 * ST)

template <int OUTMODE>
__global__ void __launch_bounds__(256, 2) mma3(
    const bf16* __restrict__ A1h, const bf16* __restrict__ A1l, int lda1,
    const bf16* __restrict__ A2h, const bf16* __restrict__ A2l, int lda2, int splitK,
    const bf16* __restrict__ Wh, const bf16* __restrict__ Wl, int ldw, int K,
    bf16* __restrict__ Chi, bf16* __restrict__ Clo, int ldc, int coff,
    const float* __restrict__ bg, const float* __restrict__ prevp,
    float* __restrict__ zbuf,
    bf16* __restrict__ rhhi, bf16* __restrict__ rhlo,
    float* __restrict__ outh)
{
    extern __shared__ char sm[];
    const uint32_t base = smem_u32(sm);
    const int t = threadIdx.x, wid = t >> 5, lane = t & 31;
    const int wm = wid & 1, wn = wid >> 1;
    const int row0 = blockIdx.y * 128, col0 = blockIdx.x * 128;
    const int chunks = K >> 5;

    auto load_stage = [&](int s, int ck) {
        int k0 = ck * 32;
        const bf16 *ah, *al;
        int lda, kk;
        if (k0 < splitK) { ah = A1h; al = A1l; lda = lda1; kk = k0; }
        else             { ah = A2h; al = A2l; lda = lda2; kk = k0 - splitK; }
        uint32_t sb = base + (uint32_t)s * ST;
#pragma unroll
        for (int half = 0; half < 2; half++) {
            int idx = t + half * 256;
            int r = idx >> 2, c = idx & 3;
            uint32_t so = r * 80 + c * 16;
            cp_async16(sb + so,          ah + (size_t)(row0 + r) * lda + kk + c * 8);
            cp_async16(sb + 10240 + so,  al + (size_t)(row0 + r) * lda + kk + c * 8);
            cp_async16(sb + 20480 + so,  Wh + (size_t)(col0 + r) * ldw + k0 + c * 8);
            cp_async16(sb + 30720 + so,  Wl + (size_t)(col0 + r) * ldw + k0 + c * 8);
        }
        cp_commit();
    };

    float acc[4][4][4];
#pragma unroll
    for (int a = 0; a < 4; a++)
#pragma unroll
        for (int b = 0; b < 4; b++)
#pragma unroll
            for (int c = 0; c < 4; c++) acc[a][b][c] = 0.f;

    load_stage(0, 0);
    if (chunks > 1) load_stage(1, 1);

    for (int i = 0; i < chunks; i++) {
        uint32_t sb = base + (uint32_t)(i & 1) * ST;
        if (i + 1 < chunks) asm volatile("cp.async.wait_group 1;" ::: "memory");
        else                asm volatile("cp.async.wait_group 0;" ::: "memory");
        __syncthreads();

#pragma unroll
        for (int ks = 0; ks < 2; ks++) {
            int kb = ks * 16;
            uint32_t ra[4][4], rbh[2][4], rbl[2][4];
            int arow[4];
            int akc = (kb >> 3) + (lane >> 4);
#pragma unroll
            for (int im = 0; im < 4; im++) {
                arow[im] = wm * 64 + im * 16 + (lane & 15);
                ldmx4(ra[im], sb + arow[im] * 80 + akc * 16);
            }
#pragma unroll
            for (int ib = 0; ib < 2; ib++) {
                int n = wn * 32 + ib * 16 + ((lane & 16) ? 8 : 0) + (lane & 7);
                int kc = (kb >> 3) + ((lane >> 3) & 1);
                ldmx4(rbh[ib], sb + 20480 + n * 80 + kc * 16);
                ldmx4(rbl[ib], sb + 30720 + n * 80 + kc * 16);
            }
#pragma unroll
            for (int im = 0; im < 4; im++)
#pragma unroll
                for (int in = 0; in < 4; in++)
                    mma16816(acc[im][in], ra[im], rbh[in >> 1][(in & 1) * 2], rbh[in >> 1][(in & 1) * 2 + 1]);
#pragma unroll
            for (int im = 0; im < 4; im++)
#pragma unroll
                for (int in = 0; in < 4; in++)
                    mma16816(acc[im][in], ra[im], rbl[in >> 1][(in & 1) * 2], rbl[in >> 1][(in & 1) * 2 + 1]);
#pragma unroll
            for (int im = 0; im < 4; im++)
                ldmx4(ra[im], sb + 10240 + arow[im] * 80 + akc * 16);
#pragma unroll
            for (int im = 0; im < 4; im++)
#pragma unroll
                for (int in = 0; in < 4; in++)
                    mma16816(acc[im][in], ra[im], rbh[in >> 1][(in & 1) * 2], rbh[in >> 1][(in & 1) * 2 + 1]);
        }
        __syncthreads();
        if (i + 2 < chunks) load_stage(i & 1, i + 2);
    }

    // ---------------- epilogue ----------------
    auto emit = [&](int mm, int cc, float v) {
        if (OUTMODE == 2) {
            split_write(Chi, Clo, (size_t)mm * ldc + coff + cc, fmaxf(v, 0.f));
        } else if (OUTMODE == 3) {
            float s = 1.f / (1.f + expf(-(v + bg[cc])));
            if (cc < 256) {
                zbuf[(size_t)mm * 256 + cc] = s;
            } else {
                int j = cc - 256;
                float rh = s * prevp[(size_t)mm * 256 + j];
                split_write(rhhi, rhlo, (size_t)mm * 256 + j, rh);
            }
        } else if (OUTMODE == 4) {
            float nv = fmaxf(v + bg[512 + cc], 0.f);
            float z = zbuf[(size_t)mm * 256 + cc];
            float pv = prevp[(size_t)mm * 256 + cc];
            outh[(size_t)mm * 256 + cc] = (1.f - z) * nv + z * pv;
        } else {  // 5: fp32 + bias
            outh[(size_t)mm * 256 + cc] = v + bg[cc];
        }
    };
#pragma unroll
    for (int im = 0; im < 4; im++) {
#pragma unroll
        for (int in = 0; in < 4; in++) {
            int m = row0 + wm * 64 + im * 16 + (lane >> 2);
            int c = col0 + wn * 32 + in * 8 + (lane & 3) * 2;
            emit(m, c, acc[im][in][0]);
            emit(m, c + 1, acc[im][in][1]);
            emit(m + 8, c, acc[im][in][2]);
            emit(m + 8, c + 1, acc[im][in][3]);
        }
    }
}

// ---------------- Mt = (Wt^T @ Ws)^T split, cvec = bt @ Ws ----------------
__global__ void computeM(const float* __restrict__ Wt, const float* __restrict__ Ws,
                         const float* __restrict__ bt,
                         bf16* __restrict__ MtH, bf16* __restrict__ MtL,
                         float* __restrict__ cvec)
{
    int k = blockIdx.x, j = threadIdx.x;
    float s = 0.f;
#pragma unroll 8
    for (int a = 0; a < 64; a++) s = fmaf(Wt[a * 256 + k], Ws[a * 256 + j], s);
    split_write(MtH, MtL, (size_t)j * 256 + k, s);   // transposed: Mt[j][k]
    if (k == 0) {
        float c = 0.f;
#pragma unroll 8
        for (int a = 0; a < 64; a++) c = fmaf(bt[a], Ws[a * 256 + j], c);
        cvec[j] = c;
    }
}

// ---------------- attention (writes in1 cols 256:512) ----------------
__global__ void __launch_bounds__(256) attn_kernel(
    const float* __restrict__ spat, const float* __restrict__ V,
    bf16* __restrict__ hi, bf16* __restrict__ lo)
{
    __shared__ float sp[NE * NH];
    __shared__ float vs[NH];
    __shared__ float attn_s[NE];
    __shared__ float ws[NE];

    int n = blockIdx.x;
    int t = threadIdx.x;

    vs[t] = V[(size_t)n * NH + t];
    const float4* g = (const float4*)(spat + (size_t)n * NE * NH);
    float4* s4 = (float4*)sp;
#pragma unroll
    for (int i = 0; i < 8; i++) s4[t + i * 256] = g[t + i * 256];
    __syncthreads();

    int warp = t >> 5, lane = t & 31;
#pragma unroll
    for (int ei = 0; ei < 4; ei++) {
        int e = warp * 4 + ei;
        float s = 0.f;
#pragma unroll
        for (int i = 0; i < 8; i++)
            s = fmaf(sp[e * NH + lane + i * 32], vs[lane + i * 32], s);
#pragma unroll
        for (int o = 16; o; o >>= 1) s += __shfl_xor_sync(0xffffffffu, s, o);
        if (lane == 0) attn_s[e] = s * 4.0f;
    }
    __syncthreads();

    if (t < 32) {
        float a = attn_s[t];
        float m = a;
#pragma unroll
        for (int o = 16; o; o >>= 1) m = fmaxf(m, __shfl_xor_sync(0xffffffffu, m, o));
        float p = expf(a - m);
        float ssum = p;
#pragma unroll
        for (int o = 16; o; o >>= 1) ssum += __shfl_xor_sync(0xffffffffu, ssum, o);
        ws[t] = p / ssum;
    }
    __syncthreads();

    float acc = 0.f;
#pragma unroll
    for (int e = 0; e < NE; e++) acc = fmaf(ws[e], sp[e * NH + t], acc);
    split_write(hi, lo, (size_t)n * 512 + 256 + t, acc);
}

// ---------------- fused prep: prev split, th split, x_e ----------------
__global__ void __launch_bounds__(256) prep_kernel(
    const float* __restrict__ prev, const float* __restrict__ th,
    const float* __restrict__ xy, const float* __restrict__ Wxy,
    bf16* __restrict__ ph, bf16* __restrict__ pl,
    bf16* __restrict__ i1h, bf16* __restrict__ i1l,
    bf16* __restrict__ ch, bf16* __restrict__ cl)
{
    int n = blockIdx.x, c = threadIdx.x;
    size_t i = (size_t)n * 256 + c;
    split_write(ph, pl, i, prev[i]);
    split_write(i1h, i1l, (size_t)n * 512 + c, th[i]);
    float x0 = xy[n * 2 + 0], x1 = xy[n * 2 + 1];
    float2 w = *(const float2*)&Wxy[c * 2];
    float v = fmaxf(fmaf(x0, w.x, x1 * w.y), 0.f);
    split_write(ch, cl, (size_t)n * 512 + c, v);
}

// ---------------- weight merge + split ----------------
__global__ void merge_weights(
    const float* __restrict__ Whe, const float* __restrict__ Wih, const float* __restrict__ Whh,
    bf16* __restrict__ WheH, bf16* __restrict__ WheL,
    bf16* __restrict__ UzrH, bf16* __restrict__ UzrL,
    bf16* __restrict__ UnH,  bf16* __restrict__ UnL)
{
    int i = blockIdx.x * 256 + threadIdx.x;
    float x;
    if (i < 131072) {
        x = Whe[i];
        split_write(WheH, WheL, i, x);
    } else if (i < 131072 + 393216) {
        int q = i - 131072;
        int j = q / 768, k = q - j * 768;
        int g = j >> 8, r = j & 255;
        x = (k < 512) ? Wih[g * 131072 + r * 512 + k] : Whh[g * 65536 + r * 256 + (k - 512)];
        split_write(UzrH, UzrL, q, x);
    } else {
        int q = i - 524288;
        int j = q / 768, k = q - j * 768;
        x = (k < 512) ? Wih[262144 + j * 512 + k] : Whh[131072 + j * 256 + (k - 512)];
        split_write(UnH, UnL, q, x);
    }
}

// ---------------- predict head ----------------
__global__ void __launch_bounds__(256) predict_kernel(
    const float* __restrict__ hid, const float* __restrict__ Wp,
    const float* __restrict__ bp, float* __restrict__ out)
{
    __shared__ float hs[NH];
    int n = blockIdx.x, t = threadIdx.x;
    hs[t] = hid[(size_t)n * NH + t];
    __syncthreads();
    int w = t >> 5, lane = t & 31;
    if (w < OUTD) {
        float s = 0.f;
#pragma unroll
        for (int i = 0; i < 8; i++)
            s = fmaf(hs[lane + i * 32], Wp[w * NH + lane + i * 32], s);
#pragma unroll
        for (int o = 16; o; o >>= 1) s += __shfl_xor_sync(0xffffffffu, s, o);
        if (lane == 0) out[(size_t)n * OUTD + w] = s + bp[w];
    }
}

// ---------------- host launcher ----------------
extern "C" void kernel_launch(void* const* d_in, const int* in_sizes, int n_in,
                              void* d_out, int out_size)
{
    const float* xy   = (const float*)d_in[0];
    const float* th   = (const float*)d_in[1];
    const float* spat = (const float*)d_in[2];
    const float* prev = (const float*)d_in[3];
    const float* Wt   = (const float*)d_in[4];
    const float* bt   = (const float*)d_in[5];
    const float* Ws   = (const float*)d_in[6];
    // d_in[7] = bs: softmax-invariant, dropped.
    const float* Wxy  = (const float*)d_in[8];
    const float* Whe  = (const float*)d_in[9];
    const float* Wih  = (const float*)d_in[10];
    const float* Whh  = (const float*)d_in[11];
    const float* bg   = (const float*)d_in[12];
    const float* Wp   = (const float*)d_in[13];
    const float* bp   = (const float*)d_in[14];

    float* out_pred   = (float*)d_out;
    float* out_hidden = (float*)d_out + NN * OUTD;

    float *pCvec, *pV, *pZ;
    bf16 *pMth, *pMtl, *pIn1h, *pIn1l, *pCath, *pCatl, *pPrevh, *pPrevl, *pRhh, *pRhl;
    bf16 *pWheh, *pWhel, *pUzrh, *pUzrl, *pUnh, *pUnl;
    cudaGetSymbolAddress((void**)&pCvec, g_cvec);
    cudaGetSymbolAddress((void**)&pV, g_V);
    cudaGetSymbolAddress((void**)&pZ, g_z);
    cudaGetSymbolAddress((void**)&pMth, g_Mt_hi);
    cudaGetSymbolAddress((void**)&pMtl, g_Mt_lo);
    cudaGetSymbolAddress((void**)&pIn1h, g_in1_hi);
    cudaGetSymbolAddress((void**)&pIn1l, g_in1_lo);
    cudaGetSymbolAddress((void**)&pCath, g_cat_hi);
    cudaGetSymbolAddress((void**)&pCatl, g_cat_lo);
    cudaGetSymbolAddress((void**)&pPrevh, g_prev_hi);
    cudaGetSymbolAddress((void**)&pPrevl, g_prev_lo);
    cudaGetSymbolAddress((void**)&pRhh, g_rh_hi);
    cudaGetSymbolAddress((void**)&pRhl, g_rh_lo);
    cudaGetSymbolAddress((void**)&pWheh, g_Whe_hi);
    cudaGetSymbolAddress((void**)&pWhel, g_Whe_lo);
    cudaGetSymbolAddress((void**)&pUzrh, g_Uzr_hi);
    cudaGetSymbolAddress((void**)&pUzrl, g_Uzr_lo);
    cudaGetSymbolAddress((void**)&pUnh, g_Un_hi);
    cudaGetSymbolAddress((void**)&pUnl, g_Un_lo);

    cudaFuncSetAttribute(mma3<2>, cudaFuncAttributeMaxDynamicSharedMemorySize, MMG_SMEM);
    cudaFuncSetAttribute(mma3<3>, cudaFuncAttributeMaxDynamicSharedMemorySize, MMG_SMEM);
    cudaFuncSetAttribute(mma3<4>, cudaFuncAttributeMaxDynamicSharedMemorySize, MMG_SMEM);
    cudaFuncSetAttribute(mma3<5>, cudaFuncAttributeMaxDynamicSharedMemorySize, MMG_SMEM);

    dim3 blk(256);
    const int MB = NN / 128;

    // prep
    merge_weights<<<2816, blk>>>(Whe, Wih, Whh, pWheh, pWhel, pUzrh, pUzrl, pUnh, pUnl);
    computeM<<<256, blk>>>(Wt, Ws, bt, pMth, pMtl, pCvec);
    prep_kernel<<<NN, blk>>>(prev, th, xy, Wxy, pPrevh, pPrevl, pIn1h, pIn1l, pCath, pCatl);

    // V = th @ Mt^T + cvec (bf16 split MMA, fp32 out)
    mma3<5><<<dim3(2, MB), blk, MMG_SMEM>>>(
        pIn1h, pIn1l, 512, pIn1h, pIn1l, 512, 1024,
        pMth, pMtl, 256, 256,
        nullptr, nullptr, 0, 0, pCvec, nullptr, nullptr, nullptr, nullptr, pV);

    // attention -> Hagg (in1 cols 256:512)
    attn_kernel<<<NN, blk>>>(spat, pV, pIn1h, pIn1l);

    // H_e = relu(in1 @ Whe^T) -> cat[:,256:512]
    mma3<2><<<dim3(2, MB), blk, MMG_SMEM>>>(
        pIn1h, pIn1l, 512, pIn1h, pIn1l, 512, 512,
        pWheh, pWhel, 512, 512,
        pCath, pCatl, 512, 256, nullptr, nullptr, nullptr, nullptr, nullptr, nullptr);

    // z,r = sigmoid([cat||prev] @ Uzr^T + bg); writes g_z and rh=r*prev
    mma3<3><<<dim3(4, MB), blk, MMG_SMEM>>>(
        pCath, pCatl, 512, pPrevh, pPrevl, 256, 512,
        pUzrh, pUzrl, 768, 768,
        nullptr, nullptr, 0, 0, bg, prev, pZ, pRhh, pRhl, nullptr);

    // n = relu([cat||rh] @ Un^T + bg); hidden -> out_hidden
    mma3<4><<<dim3(2, MB), blk, MMG_SMEM>>>(
        pCath, pCatl, 512, pRhh, pRhl, 256, 512,
        pUnh, pUnl, 768, 768,
        nullptr, nullptr, 0, 0, bg, prev, pZ, nullptr, nullptr, out_hidden);

    // predict head
    predict_kernel<<<NN, blk>>>(out_hidden, Wp, bp, out_pred);
}